// round 1
// baseline (speedup 1.0000x reference)
#include <cuda_runtime.h>

// Problem constants
#define B_   256
#define T_   256
#define C_   384
#define NH_  8
#define HD_  48

// Scratch (static __device__ arrays — no allocation APIs allowed)
__device__ float g_q[B_ * NH_ * T_ * HD_];    // [B, NH, T, HD]
__device__ float g_k[B_ * NH_ * T_ * HD_];
__device__ float g_v[B_ * NH_ * T_ * HD_];
__device__ float g_att[B_ * T_ * C_];         // attention output, [B*T, C]

// ---------------------------------------------------------------------------
// 128x128x8 register-blocked SGEMM:  C[n,o] = sum_k A[n,k] * W[o,k] + bias[o]
// A is row-major [N, K] (K contiguous), W is row-major [O, K] (K contiguous).
// MODE 0: QKV epilogue — scatter into g_q/g_k/g_v in head-major layout.
// MODE 1: proj epilogue — A is g_att (param ignored), linear store to out.
// ---------------------------------------------------------------------------
template <int MODE>
__global__ __launch_bounds__(256) void sgemm_kernel(
    const float* __restrict__ A,
    const float* __restrict__ W,
    const float* __restrict__ bias,
    float* __restrict__ out)
{
    const int K = C_;  // 384 for both GEMMs

    __shared__ float As[8][128];
    __shared__ float Bs[8][128];

    const int tid = threadIdx.x;
    const int n0 = blockIdx.x * 128;
    const int o0 = blockIdx.y * 128;

    const int tx = tid & 15;      // 0..15 (column group)
    const int ty = tid >> 4;      // 0..15 (row group)

    const int lr = tid >> 1;          // 0..127 tile row for loads
    const int lc = (tid & 1) * 4;     // 0 or 4 within k-slab

    const float* Ap = (MODE == 1) ? (const float*)g_att : A;

    const float* aptr = Ap + (size_t)(n0 + lr) * K + lc;
    const float* bptr = W  + (size_t)(o0 + lr) * K + lc;

    float acc[8][8];
#pragma unroll
    for (int i = 0; i < 8; ++i)
#pragma unroll
        for (int j = 0; j < 8; ++j) acc[i][j] = 0.f;

    for (int k0 = 0; k0 < K; k0 += 8) {
        const float4 a4 = *(const float4*)(aptr + k0);
        const float4 b4 = *(const float4*)(bptr + k0);

        __syncthreads();
        As[lc + 0][lr] = a4.x; As[lc + 1][lr] = a4.y;
        As[lc + 2][lr] = a4.z; As[lc + 3][lr] = a4.w;
        Bs[lc + 0][lr] = b4.x; Bs[lc + 1][lr] = b4.y;
        Bs[lc + 2][lr] = b4.z; Bs[lc + 3][lr] = b4.w;
        __syncthreads();

#pragma unroll
        for (int k = 0; k < 8; ++k) {
            const float4 a0 = *(const float4*)&As[k][ty * 8];
            const float4 a1 = *(const float4*)&As[k][ty * 8 + 4];
            const float4 b0 = *(const float4*)&Bs[k][tx * 8];
            const float4 b1 = *(const float4*)&Bs[k][tx * 8 + 4];
            const float ar[8] = {a0.x, a0.y, a0.z, a0.w, a1.x, a1.y, a1.z, a1.w};
            const float br[8] = {b0.x, b0.y, b0.z, b0.w, b1.x, b1.y, b1.z, b1.w};
#pragma unroll
            for (int i = 0; i < 8; ++i)
#pragma unroll
                for (int j = 0; j < 8; ++j)
                    acc[i][j] = fmaf(ar[i], br[j], acc[i][j]);
        }
    }

    // Epilogue
#pragma unroll
    for (int i = 0; i < 8; ++i) {
        const int n = n0 + ty * 8 + i;
        if (MODE == 0) {
            const int bb = n / T_;
            const int t  = n - bb * T_;
#pragma unroll
            for (int j = 0; j < 8; ++j) {
                const int o = o0 + tx * 8 + j;
                const float v = acc[i][j] + bias[o];
                const int part = o / C_;          // 0=q, 1=k, 2=v
                const int c0 = o - part * C_;
                const int h = c0 / HD_;
                const int d = c0 - h * HD_;
                float* dst = (part == 0) ? g_q : ((part == 1) ? g_k : g_v);
                dst[(((size_t)bb * NH_ + h) * T_ + t) * HD_ + d] = v;
            }
        } else {
#pragma unroll
            for (int j = 0; j < 8; ++j) {
                const int o = o0 + tx * 8 + j;
                out[(size_t)n * C_ + o] = acc[i][j] + bias[o];
            }
        }
    }
}

// ---------------------------------------------------------------------------
// Causal flash attention: 1 thread = 1 query row. Online softmax over 16-key
// shared-memory chunks. grid = (B*NH, T/128), block = 128.
// ---------------------------------------------------------------------------
__global__ __launch_bounds__(128) void attn_kernel()
{
    const int bh = blockIdx.x;            // 0..B*NH-1
    const int q0 = blockIdx.y * 128;
    const int tid = threadIdx.x;
    const int qi = q0 + tid;              // this thread's query index

    __shared__ float Ks[16][HD_];
    __shared__ float Vs[16][HD_];

    const float* qp = g_q + ((size_t)bh * T_ + qi) * HD_;
    float qreg[HD_];
#pragma unroll
    for (int d = 0; d < HD_; ++d) qreg[d] = qp[d];

    float acc[HD_];
#pragma unroll
    for (int d = 0; d < HD_; ++d) acc[d] = 0.f;

    float m = -1e30f;
    float l = 0.f;
    const float scale = 0.14433756729740643f;  // 1/sqrt(48)

    const int kend = q0 + 128;  // max key any thread in this block needs (exclusive)

    for (int kc = 0; kc < kend; kc += 16) {
        // cooperative chunk load: 16 rows x 48 floats = 192 float4
        const float4* kg = (const float4*)(g_k + ((size_t)bh * T_ + kc) * HD_);
        const float4* vg = (const float4*)(g_v + ((size_t)bh * T_ + kc) * HD_);
        float4* ks4 = (float4*)&Ks[0][0];
        float4* vs4 = (float4*)&Vs[0][0];
        __syncthreads();
        for (int i = tid; i < 192; i += 128) {
            ks4[i] = kg[i];
            vs4[i] = vg[i];
        }
        __syncthreads();

        if (kc <= qi) {
            float s[16];
            float mc = -1e30f;
#pragma unroll
            for (int j = 0; j < 16; ++j) {
                float dot = 0.f;
#pragma unroll
                for (int d = 0; d < HD_; ++d)
                    dot = fmaf(qreg[d], Ks[j][d], dot);
                s[j] = (kc + j <= qi) ? dot * scale : -1e30f;
                mc = fmaxf(mc, s[j]);
            }
            const float newm = fmaxf(m, mc);
            const float f = __expf(m - newm);
            l *= f;
#pragma unroll
            for (int d = 0; d < HD_; ++d) acc[d] *= f;
#pragma unroll
            for (int j = 0; j < 16; ++j) {
                const float p = __expf(s[j] - newm);
                l += p;
#pragma unroll
                for (int d = 0; d < HD_; ++d)
                    acc[d] = fmaf(p, Vs[j][d], acc[d]);
            }
            m = newm;
        }
    }

    const float inv = 1.f / l;
    const int bb = bh / NH_;
    const int h  = bh - bb * NH_;
    float* op = g_att + ((size_t)bb * T_ + qi) * C_ + h * HD_;
#pragma unroll
    for (int d = 0; d < HD_; ++d) op[d] = acc[d] * inv;
}

// ---------------------------------------------------------------------------
extern "C" void kernel_launch(void* const* d_in, const int* in_sizes, int n_in,
                              void* d_out, int out_size)
{
    const float* x      = (const float*)d_in[0];  // [B,T,C]
    const float* attn_w = (const float*)d_in[1];  // [3C, C]
    const float* attn_b = (const float*)d_in[2];  // [3C]
    const float* proj_w = (const float*)d_in[3];  // [C, C]
    const float* proj_b = (const float*)d_in[4];  // [C]
    float* out = (float*)d_out;                   // [B,T,C]

    // Stage 1: QKV projection + head-major scatter
    {
        dim3 grid(B_ * T_ / 128, (3 * C_) / 128);  // (512, 9)
        sgemm_kernel<0><<<grid, 256>>>(x, attn_w, attn_b, nullptr);
    }
    // Stage 2: causal attention
    {
        dim3 grid(B_ * NH_, T_ / 128);             // (2048, 2)
        attn_kernel<<<grid, 128>>>();
    }
    // Stage 3: output projection
    {
        dim3 grid(B_ * T_ / 128, C_ / 128);        // (512, 3)
        sgemm_kernel<1><<<grid, 256>>>(nullptr, proj_w, proj_b, out);
    }
}

// round 2
// speedup vs baseline: 1.3612x; 1.3612x over previous
#include <cuda_runtime.h>
#include <cstdint>

// Problem constants
#define B_   256
#define T_   256
#define C_   384
#define NH_  8
#define HD_  48

// Scratch (static __device__ arrays — no allocation APIs allowed)
__device__ float g_q[B_ * NH_ * T_ * HD_];    // [B, NH, T, HD]
__device__ float g_k[B_ * NH_ * T_ * HD_];
__device__ float g_v[B_ * NH_ * T_ * HD_];
__device__ float g_att[B_ * T_ * C_];         // attention output, [B*T, C]

// ---------------------------------------------------------------------------
// tf32 helpers
// ---------------------------------------------------------------------------
__device__ __forceinline__ uint32_t f2tf32(float x) {
    uint32_t r;
    asm("cvt.rna.tf32.f32 %0, %1;" : "=r"(r) : "f"(x));
    return r;
}

__device__ __forceinline__ void mma_tf32(float c[4], const uint32_t a[4], const uint32_t b[2]) {
    asm volatile(
        "mma.sync.aligned.m16n8k8.row.col.f32.tf32.tf32.f32 "
        "{%0,%1,%2,%3}, {%4,%5,%6,%7}, {%8,%9}, {%0,%1,%2,%3};\n"
        : "+f"(c[0]), "+f"(c[1]), "+f"(c[2]), "+f"(c[3])
        : "r"(a[0]), "r"(a[1]), "r"(a[2]), "r"(a[3]),
          "r"(b[0]), "r"(b[1]));
}

// ---------------------------------------------------------------------------
// Tensor-core GEMM (3xTF32 compensated):  C[n,o] = sum_k A[n,k]*W[o,k] + bias[o]
// A row-major [N,K] (K contig), W row-major [O,K] (K contig, acts as col-major B).
// Block tile 128(M) x 64(N), BK=16, 256 threads = 8 warps, warp tile 32x32.
// MODE 0: QKV epilogue — scatter into g_q/g_k/g_v head-major.
// MODE 1: proj epilogue — A := g_att, linear store + bias.
// ---------------------------------------------------------------------------
#define BM 128
#define BN 64
#define BK 16
#define APAD 4   // row length BK+APAD = 20 floats (16B-aligned rows, conflict-free quads)

template <int MODE>
__global__ __launch_bounds__(256) void tgemm_kernel(
    const float* __restrict__ A,
    const float* __restrict__ W,
    const float* __restrict__ bias,
    float* __restrict__ out)
{
    const int K = C_;  // 384

    __shared__ float As[BM][BK + APAD];
    __shared__ float Ws[BN][BK + APAD];

    const int tid  = threadIdx.x;
    const int wid  = tid >> 5;
    const int lane = tid & 31;
    const int gid  = lane >> 2;   // 0..7
    const int tig  = lane & 3;    // 0..3

    const int warpM = wid & 3;    // 0..3  -> 4*32 = 128 rows
    const int warpN = wid >> 2;   // 0..1  -> 2*32 = 64 cols

    const int n0 = blockIdx.x * BM;
    const int o0 = blockIdx.y * BN;

    const float* Ap = (MODE == 1) ? (const float*)g_att : A;

    float acc[2][4][4];
#pragma unroll
    for (int mi = 0; mi < 2; ++mi)
#pragma unroll
        for (int ni = 0; ni < 4; ++ni)
#pragma unroll
            for (int c = 0; c < 4; ++c) acc[mi][ni][c] = 0.f;

    // gmem->smem load mapping (per BK=16 slab):
    // A tile: 128 rows x 16 cols = 512 float4; thread does 2 (i = 2*tid, 2*tid+1)
    // W tile:  64 rows x 16 cols = 256 float4; thread does 1
    const int am0 = (2 * tid) >> 2;         // = tid/2
    const int ak0 = ((2 * tid) & 3) * 4;    // 0,8 pattern per parity
    const int am1 = (2 * tid + 1) >> 2;
    const int ak1 = ((2 * tid + 1) & 3) * 4;
    const int wm  = tid >> 2;
    const int wk  = (tid & 3) * 4;

    for (int k0 = 0; k0 < K; k0 += BK) {
        const float4 a0 = *(const float4*)(Ap + (size_t)(n0 + am0) * K + k0 + ak0);
        const float4 a1 = *(const float4*)(Ap + (size_t)(n0 + am1) * K + k0 + ak1);
        const float4 w0 = *(const float4*)(W  + (size_t)(o0 + wm ) * K + k0 + wk);

        __syncthreads();
        *(float4*)&As[am0][ak0] = a0;
        *(float4*)&As[am1][ak1] = a1;
        *(float4*)&Ws[wm][wk]   = w0;
        __syncthreads();

#pragma unroll
        for (int kk = 0; kk < BK; kk += 8) {
            // Load + split A fragments (2 m-tiles)
            uint32_t Ahi[2][4], Alo[2][4];
#pragma unroll
            for (int mi = 0; mi < 2; ++mi) {
                const int r0 = warpM * 32 + mi * 16 + gid;
                const int r1 = r0 + 8;
                const float f0 = As[r0][kk + tig];
                const float f1 = As[r1][kk + tig];
                const float f2 = As[r0][kk + tig + 4];
                const float f3 = As[r1][kk + tig + 4];
                Ahi[mi][0] = f2tf32(f0); Alo[mi][0] = f2tf32(f0 - __uint_as_float(Ahi[mi][0]));
                Ahi[mi][1] = f2tf32(f1); Alo[mi][1] = f2tf32(f1 - __uint_as_float(Ahi[mi][1]));
                Ahi[mi][2] = f2tf32(f2); Alo[mi][2] = f2tf32(f2 - __uint_as_float(Ahi[mi][2]));
                Ahi[mi][3] = f2tf32(f3); Alo[mi][3] = f2tf32(f3 - __uint_as_float(Ahi[mi][3]));
            }
            // Load + split B fragments (4 n-tiles)
            uint32_t Bhi[4][2], Blo[4][2];
#pragma unroll
            for (int ni = 0; ni < 4; ++ni) {
                const int r = warpN * 32 + ni * 8 + gid;
                const float f0 = Ws[r][kk + tig];
                const float f1 = Ws[r][kk + tig + 4];
                Bhi[ni][0] = f2tf32(f0); Blo[ni][0] = f2tf32(f0 - __uint_as_float(Bhi[ni][0]));
                Bhi[ni][1] = f2tf32(f1); Blo[ni][1] = f2tf32(f1 - __uint_as_float(Bhi[ni][1]));
            }
#pragma unroll
            for (int mi = 0; mi < 2; ++mi)
#pragma unroll
                for (int ni = 0; ni < 4; ++ni) {
                    mma_tf32(acc[mi][ni], Ahi[mi], Bhi[ni]);
                    mma_tf32(acc[mi][ni], Alo[mi], Bhi[ni]);
                    mma_tf32(acc[mi][ni], Ahi[mi], Blo[ni]);
                }
        }
    }

    // Epilogue. C-frag mapping: c0,c1 -> row gid, cols 2*tig,2*tig+1 ; c2,c3 -> row gid+8.
#pragma unroll
    for (int mi = 0; mi < 2; ++mi) {
#pragma unroll
        for (int ci = 0; ci < 2; ++ci) {
            const int row = n0 + warpM * 32 + mi * 16 + gid + ci * 8;
#pragma unroll
            for (int ni = 0; ni < 4; ++ni) {
#pragma unroll
                for (int cj = 0; cj < 2; ++cj) {
                    const int col = o0 + warpN * 32 + ni * 8 + tig * 2 + cj;
                    const float v = acc[mi][ni][ci * 2 + cj] + bias[col];
                    if (MODE == 0) {
                        const int bb = row / T_;
                        const int t  = row - bb * T_;
                        const int part = col / C_;          // 0=q, 1=k, 2=v
                        const int c0 = col - part * C_;
                        const int h = c0 / HD_;
                        const int d = c0 - h * HD_;
                        float* dst = (part == 0) ? g_q : ((part == 1) ? g_k : g_v);
                        dst[(((size_t)bb * NH_ + h) * T_ + t) * HD_ + d] = v;
                    } else {
                        out[(size_t)row * C_ + col] = v;
                    }
                }
            }
        }
    }
}

// ---------------------------------------------------------------------------
// Causal flash attention: 1 thread = 1 query row. Online softmax over 16-key
// shared-memory chunks. grid = (B*NH, T/128), block = 128.
// ---------------------------------------------------------------------------
__global__ __launch_bounds__(128) void attn_kernel()
{
    const int bh = blockIdx.x;            // 0..B*NH-1
    const int q0 = blockIdx.y * 128;
    const int tid = threadIdx.x;
    const int qi = q0 + tid;              // this thread's query index

    __shared__ float Ks[16][HD_];
    __shared__ float Vs[16][HD_];

    const float* qp = g_q + ((size_t)bh * T_ + qi) * HD_;
    float qreg[HD_];
#pragma unroll
    for (int d = 0; d < HD_; ++d) qreg[d] = qp[d];

    float acc[HD_];
#pragma unroll
    for (int d = 0; d < HD_; ++d) acc[d] = 0.f;

    float m = -1e30f;
    float l = 0.f;
    const float scale = 0.14433756729740643f;  // 1/sqrt(48)

    const int kend = q0 + 128;  // max key any thread in this block needs (exclusive)

    for (int kc = 0; kc < kend; kc += 16) {
        const float4* kg = (const float4*)(g_k + ((size_t)bh * T_ + kc) * HD_);
        const float4* vg = (const float4*)(g_v + ((size_t)bh * T_ + kc) * HD_);
        float4* ks4 = (float4*)&Ks[0][0];
        float4* vs4 = (float4*)&Vs[0][0];
        __syncthreads();
        for (int i = tid; i < 192; i += 128) {
            ks4[i] = kg[i];
            vs4[i] = vg[i];
        }
        __syncthreads();

        if (kc <= qi) {
            float s[16];
            float mc = -1e30f;
#pragma unroll
            for (int j = 0; j < 16; ++j) {
                float dot = 0.f;
#pragma unroll
                for (int d = 0; d < HD_; ++d)
                    dot = fmaf(qreg[d], Ks[j][d], dot);
                s[j] = (kc + j <= qi) ? dot * scale : -1e30f;
                mc = fmaxf(mc, s[j]);
            }
            const float newm = fmaxf(m, mc);
            const float f = __expf(m - newm);
            l *= f;
#pragma unroll
            for (int d = 0; d < HD_; ++d) acc[d] *= f;
#pragma unroll
            for (int j = 0; j < 16; ++j) {
                const float p = __expf(s[j] - newm);
                l += p;
#pragma unroll
                for (int d = 0; d < HD_; ++d)
                    acc[d] = fmaf(p, Vs[j][d], acc[d]);
            }
            m = newm;
        }
    }

    const float inv = 1.f / l;
    const int bb = bh / NH_;
    const int h  = bh - bb * NH_;
    float* op = g_att + ((size_t)bb * T_ + qi) * C_ + h * HD_;
#pragma unroll
    for (int d = 0; d < HD_; ++d) op[d] = acc[d] * inv;
}

// ---------------------------------------------------------------------------
extern "C" void kernel_launch(void* const* d_in, const int* in_sizes, int n_in,
                              void* d_out, int out_size)
{
    const float* x      = (const float*)d_in[0];  // [B,T,C]
    const float* attn_w = (const float*)d_in[1];  // [3C, C]
    const float* attn_b = (const float*)d_in[2];  // [3C]
    const float* proj_w = (const float*)d_in[3];  // [C, C]
    const float* proj_b = (const float*)d_in[4];  // [C]
    float* out = (float*)d_out;                   // [B,T,C]

    // Stage 1: QKV projection + head-major scatter
    {
        dim3 grid(B_ * T_ / BM, (3 * C_) / BN);   // (512, 18)
        tgemm_kernel<0><<<grid, 256>>>(x, attn_w, attn_b, nullptr);
    }
    // Stage 2: causal attention
    {
        dim3 grid(B_ * NH_, T_ / 128);            // (2048, 2)
        attn_kernel<<<grid, 128>>>();
    }
    // Stage 3: output projection
    {
        dim3 grid(B_ * T_ / BM, C_ / BN);         // (512, 6)
        tgemm_kernel<1><<<grid, 256>>>(nullptr, proj_w, proj_b, out);
    }
}